// round 6
// baseline (speedup 1.0000x reference)
#include <cuda_runtime.h>
#include <cstdint>

// ---------------- problem constants ----------------
#define BB 4
#define CC 256
#define HH 96
#define WW 320
#define HW (HH * WW)          // 30720
#define MT 32                 // queries per CTA (halved for 2 CTAs/SM)
#define KC 16                 // K per chunk (one mma k-step)
#define NCHUNK (CC / KC)      // 16
#define NTH 256
#define RAD 4
#define NCH 36
#define VOL_STRIDE 322

// ---------------- smem layout (bytes) ----------------
#define BSTR 656              // B row stride: 328 halves (16B-aligned, odd/16 -> conflict-free)
#define ASTR 80               // A row stride: 40 halves (16x5, odd/16)
#define OFF_BH 0
#define OFF_BL (KC * BSTR)            // 10496
#define OFF_AH (2 * KC * BSTR)        // 20992
#define OFF_AL (OFF_AH + KC * ASTR)   // 22272
#define STAGE_BYTES (OFF_AL + KC * ASTR)       // 23552 (x2 stages = 47104)
#define VOL_BYTES (MT * VOL_STRIDE * 4)        // 41216
#define SMEM_BYTES (2 * STAGE_BYTES)           // 47104 (vol overlays stages)

static __device__ __forceinline__ uint32_t smem_u32(const void* p) {
    uint32_t a;
    asm("{ .reg .u64 t; cvta.to.shared.u64 t, %1; cvt.u32.u64 %0, t; }" : "=r"(a) : "l"(p));
    return a;
}

static __device__ __forceinline__ void ldsm4t(uint32_t* r, uint32_t a) {
    asm volatile("ldmatrix.sync.aligned.m8n8.x4.trans.shared.b16 {%0,%1,%2,%3}, [%4];"
                 : "=r"(r[0]), "=r"(r[1]), "=r"(r[2]), "=r"(r[3]) : "r"(a));
}
static __device__ __forceinline__ void ldsm2t(uint32_t* r, uint32_t a) {
    asm volatile("ldmatrix.sync.aligned.m8n8.x2.trans.shared.b16 {%0,%1}, [%2];"
                 : "=r"(r[0]), "=r"(r[1]) : "r"(a));
}
static __device__ __forceinline__ void mma16816(float* d, const uint32_t* a, const uint32_t* b) {
    asm volatile("mma.sync.aligned.m16n8k16.row.col.f32.bf16.bf16.f32 "
                 "{%0,%1,%2,%3}, {%4,%5,%6,%7}, {%8,%9}, {%0,%1,%2,%3};"
                 : "+f"(d[0]), "+f"(d[1]), "+f"(d[2]), "+f"(d[3])
                 : "r"(a[0]), "r"(a[1]), "r"(a[2]), "r"(a[3]), "r"(b[0]), "r"(b[1]));
}

// float4 -> hi (exact bf16 truncation) + lo (bf16 residual); two STS.64.
static __device__ __forceinline__ void cvt_sts(uint32_t hi_a, uint32_t lo_a, float4 x) {
    uint32_t u0 = __float_as_uint(x.x), u1 = __float_as_uint(x.y);
    uint32_t u2 = __float_as_uint(x.z), u3 = __float_as_uint(x.w);
    uint32_t h0, h1;
    asm("prmt.b32 %0, %1, %2, 0x7632;" : "=r"(h0) : "r"(u0), "r"(u1));
    asm("prmt.b32 %0, %1, %2, 0x7632;" : "=r"(h1) : "r"(u2), "r"(u3));
    float f0 = x.x - __uint_as_float(u0 & 0xffff0000u);
    float f1 = x.y - __uint_as_float(u1 & 0xffff0000u);
    float f2 = x.z - __uint_as_float(u2 & 0xffff0000u);
    float f3 = x.w - __uint_as_float(u3 & 0xffff0000u);
    uint32_t l0, l1;
    asm("cvt.rn.bf16x2.f32 %0, %1, %2;" : "=r"(l0) : "f"(f1), "f"(f0));
    asm("cvt.rn.bf16x2.f32 %0, %1, %2;" : "=r"(l1) : "f"(f3), "f"(f2));
    asm volatile("st.shared.v2.b32 [%0], {%1,%2};" :: "r"(hi_a), "r"(h0), "r"(h1) : "memory");
    asm volatile("st.shared.v2.b32 [%0], {%1,%2};" :: "r"(lo_a), "r"(l0), "r"(l1) : "memory");
}

__device__ __forceinline__ float pooled(const float* __restrict__ row, int i, int lvl, int Wl) {
    if (i < 0 || i >= Wl) return 0.0f;
    const int sz = 1 << lvl;
    const float* p = row + (i << lvl);
    float s = 0.0f;
#pragma unroll 8
    for (int k = 0; k < sz; ++k) s += p[k];
    return s * (1.0f / (float)sz);
}

__global__ void __launch_bounds__(NTH, 2)
corr_hmma_kernel(const float* __restrict__ fmap1, const float* __restrict__ fmap2,
                 const float* __restrict__ cents, float* __restrict__ out) {
    extern __shared__ char smem[];
    const uint32_t sb = smem_u32(smem);
    const int t = threadIdx.x, wid = t >> 5, lid = t & 31;
    const int q0 = blockIdx.x * MT, h = blockIdx.y, b = blockIdx.z;

    // ---- B load mapping: thread -> (channel-in-chunk, float4 position) ----
    const int ch  = t >> 4;   // 0..15
    const int pos = t & 15;   // 0..15
    const float* Bg = fmap2 + ((size_t)b * CC + ch) * HW + (size_t)h * WW + 4 * pos;
    // ---- A load mapping: threads 0..127 -> (ch, pos4 in 0..7) ----
    const int cha  = t >> 3;          // 0..31 (only t<128 valid -> 0..15)
    const int posa = t & 7;
    const float* Ag = fmap1 + ((size_t)b * CC + cha) * HW + (size_t)h * WW + q0 + 4 * posa;

    // ---- per-lane ldmatrix offsets ----
    const int r8 = lid & 7, tl = lid >> 3;
    const uint32_t laneA = (uint32_t)((r8 + 8 * (tl >> 1)) * ASTR + (tl & 1) * 16);
    const uint32_t laneB = (uint32_t)((r8 + 8 * (tl & 1)) * BSTR + (tl >> 1) * 16);
    const uint32_t nbase = (uint32_t)(80 * wid);  // n = 40*wid

    const uint32_t sts_ah = sb + OFF_AH + (uint32_t)(cha * ASTR + 8 * posa);
    const uint32_t sts_al = sb + OFF_AL + (uint32_t)(cha * ASTR + 8 * posa);
    const uint32_t sts_bh = sb + OFF_BH + (uint32_t)(ch * BSTR + 8 * pos);
    const uint32_t sts_bl = sb + OFF_BL + (uint32_t)(ch * BSTR + 8 * pos);

    float acc[2][5][4];
#pragma unroll
    for (int i = 0; i < 2; ++i)
#pragma unroll
        for (int j = 0; j < 5; ++j)
#pragma unroll
            for (int k2 = 0; k2 < 4; ++k2) acc[i][j][k2] = 0.0f;

    float4 ra, rb[5];
    // chunk 0: load + stage into buf0
    if (t < 128) ra = *(const float4*)Ag;
#pragma unroll
    for (int j = 0; j < 5; ++j) rb[j] = *(const float4*)(Bg + 64 * j);
    if (t < 128) cvt_sts(sts_ah, sts_al, ra);
#pragma unroll
    for (int j = 0; j < 5; ++j) cvt_sts(sts_bh + 128u * j, sts_bl + 128u * j, rb[j]);
    __syncthreads();
    // prefetch chunk 1
    {
        const size_t o = (size_t)KC * HW;
        if (t < 128) ra = *(const float4*)(Ag + o);
#pragma unroll
        for (int j = 0; j < 5; ++j) rb[j] = *(const float4*)(Bg + o + 64 * j);
    }

    for (int kc = 0; kc < NCHUNK; ++kc) {
        const uint32_t cur = sb + (uint32_t)((kc & 1) * STAGE_BYTES);
        const uint32_t nxt = (uint32_t)(((kc + 1) & 1) * STAGE_BYTES);

        // ---- fragment loads (each plane once) ----
        uint32_t ah[2][4], al[2][4], bh[10], bl[10];
        {
            const uint32_t abh = cur + OFF_AH + laneA;
            const uint32_t abl = cur + OFF_AL + laneA;
#pragma unroll
            for (int i = 0; i < 2; ++i) {
                ldsm4t(ah[i], abh + 32u * i);
                ldsm4t(al[i], abl + 32u * i);
            }
            const uint32_t bbh = cur + OFF_BH + laneB + nbase;
            const uint32_t bbl = cur + OFF_BL + laneB + nbase;
            ldsm4t(bh + 0, bbh); ldsm4t(bh + 4, bbh + 32u); ldsm2t(bh + 8, bbh + 64u);
            ldsm4t(bl + 0, bbl); ldsm4t(bl + 4, bbl + 32u); ldsm2t(bl + 8, bbl + 64u);
        }

        // ---- stage chunk kc+1 into opposite buffer (drains under MMAs) ----
        if (kc + 1 < NCHUNK) {
            if (t < 128) cvt_sts(sts_ah + nxt, sts_al + nxt, ra);
#pragma unroll
            for (int j = 0; j < 5; ++j)
                cvt_sts(sts_bh + nxt + 128u * j, sts_bl + nxt + 128u * j, rb[j]);
            // ---- issue LDGs for chunk kc+2 (covered by MMA phase) ----
            if (kc + 2 < NCHUNK) {
                const size_t o = (size_t)(kc + 2) * KC * HW;
                if (t < 128) ra = *(const float4*)(Ag + o);
#pragma unroll
                for (int j = 0; j < 5; ++j) rb[j] = *(const float4*)(Bg + o + 64 * j);
            }
        }

        // ---- 30 MMAs: (Ah,Bh), (Ah,Bl), (Al,Bh) ----
#pragma unroll
        for (int i = 0; i < 2; ++i)
#pragma unroll
            for (int j = 0; j < 5; ++j) {
                mma16816(acc[i][j], ah[i], bh + 2 * j);
                mma16816(acc[i][j], ah[i], bl + 2 * j);
                mma16816(acc[i][j], al[i], bh + 2 * j);
            }

        __syncthreads();  // all frags read + all STS drained before buffer reuse
    }

    // ---- accumulators -> vol (overlays stage smem) ----
    float* vol = (float*)smem;
    {
        const int mr = lid >> 2, nc0 = 2 * (lid & 3);
        const float s = 0.0625f;  // 1/sqrt(256)
#pragma unroll
        for (int i = 0; i < 2; ++i)
#pragma unroll
            for (int j = 0; j < 5; ++j) {
                const int q = 16 * i + mr, v = 40 * wid + 8 * j + nc0;
                *(float2*)&vol[q * VOL_STRIDE + v] =
                    make_float2(acc[i][j][0] * s, acc[i][j][1] * s);
                *(float2*)&vol[(q + 8) * VOL_STRIDE + v] =
                    make_float2(acc[i][j][2] * s, acc[i][j][3] * s);
            }
    }
    __syncthreads();

    // ---- pyramid sampling: 32 q x 36 ch ----
    const int q = t & 31, grp = t >> 5;  // 8 groups
    const float cent = cents[((size_t)b * HH + h) * WW + q0 + q];
    const float* row = vol + q * VOL_STRIDE;
#pragma unroll
    for (int rep = 0; rep < 5; ++rep) {
        const int chn = grp + 8 * rep;
        if (chn >= NCH) break;
        const int lvl = chn / 9, tap = chn - 9 * lvl;
        const int Wl = WW >> lvl;
        const float x  = cent * (1.0f / (float)(1 << lvl)) + (float)(tap - RAD);
        const float x0 = floorf(x);
        const float tt = x - x0;
        const int   i0 = (int)x0;
        const float p0 = pooled(row, i0, lvl, Wl);
        const float p1 = pooled(row, i0 + 1, lvl, Wl);
        out[(((size_t)b * NCH + chn) * HH + h) * WW + q0 + q] = p0 * (1.0f - tt) + p1 * tt;
    }
}

extern "C" void kernel_launch(void* const* d_in, const int* in_sizes, int n_in,
                              void* d_out, int out_size) {
    const float* fmap1 = (const float*)d_in[0];
    const float* fmap2 = (const float*)d_in[1];
    const float* cents = (const float*)d_in[2];
    float* out = (float*)d_out;

    cudaFuncSetAttribute(corr_hmma_kernel,
                         cudaFuncAttributeMaxDynamicSharedMemorySize, SMEM_BYTES);

    dim3 grid(WW / MT, HH, BB);  // (10, 96, 4)
    corr_hmma_kernel<<<grid, NTH, SMEM_BYTES>>>(fmap1, fmap2, cents, out);
}